// round 2
// baseline (speedup 1.0000x reference)
#include <cuda_runtime.h>
#include <cuda_bf16.h>
#include <math.h>

// EdgeEmbeddingBlock: out_r[b,k,i,j] = radial[b,i] * na[b,k] * ylm_r[b,j]
//                     out_i[b,k,i,j] = radial[b,i] * na[b,k] * ylm_i[b,j]
// E=60000, K=10, NMAX=8, J=16. Output [combined_r | combined_i], 614 MB written.
// Persistent warps: each warp grid-strides over edges, so per-edge setup math
// overlaps with the previous edge's in-flight streaming stores.

#define NMAX 8
#define KATTR 10
#define ELEMS_PER_EDGE (KATTR * NMAX * 16)     // 1280 floats
#define F4_PER_EDGE (ELEMS_PER_EDGE / 4)       // 320 float4

#define NWARPS_CTA 8
#define NCTAS 1024

__global__ __launch_bounds__(NWARPS_CTA * 32, 4)
void edge_embed_kernel(const int* __restrict__ edge_index,
                       const float* __restrict__ lens,
                       const float* __restrict__ vecs,
                       const float* __restrict__ attrs,
                       float* __restrict__ out,
                       int E)
{
    __shared__ float  s_rad[NWARPS_CTA][8];
    __shared__ float  s_na[NWARPS_CTA][12];
    __shared__ float  s_scal[NWARPS_CTA][80];
    __shared__ float4 s_ylr[NWARPS_CTA][4];
    __shared__ float4 s_yli[NWARPS_CTA][4];

    const int warp = threadIdx.x >> 5;
    const int lane = threadIdx.x & 31;
    const int gwarp  = blockIdx.x * NWARPS_CTA + warp;
    const int nwarps = gridDim.x * NWARPS_CTA;

    float4* __restrict__ out4 = (float4*)out;

    for (int e = gwarp; e < E; e += nwarps) {
        // ---- per-edge scalars (broadcast loads) ----
        const float x  = lens[e];
        const float vx = vecs[3 * e + 0];
        const float vy = vecs[3 * e + 1];
        const float vz = vecs[3 * e + 2];
        const int sender = edge_index[e];   // edge_index[0, e]

        // ---- radial envelope (poly cutoff p=6, R_CUT=5) ----
        const float u  = x * 0.2f;
        const float u2 = u * u, u3 = u2 * u;
        const float u6 = u3 * u3, u7 = u6 * u, u8 = u7 * u;
        float env = 1.0f - 28.0f * u6 + 48.0f * u7 - 21.0f * u8;
        env = (u < 1.0f) ? env : 0.0f;
        const float base = 0.63245553203f * env / x;   // sqrt(2/5) * env / x

        if (lane < 8) {
            const float w = (float)(lane + 1) * 0.62831853071f;  // n*pi/R_CUT
            s_rad[warp][lane] = base * sinf(w * x);
        }
        if (lane >= 8 && lane < 8 + KATTR) {
            s_na[warp][lane - 8] = attrs[sender * KATTR + (lane - 8)];
        }

        // ---- zonal harmonics (lane 0 publishes) ----
        {
            const float nrm = sqrtf(vx * vx + vy * vy + vz * vz);
            const float inv = 1.0f / fmaxf(nrm, 1e-9f);
            const float ux = vx * inv, uy = vy * inv, uz = vz * inv;
            const float ct  = uz;
            const float st2 = fmaxf(1.0f - ct * ct, 0.0f);
            const float st  = sqrtf(st2);
            const float rxy = sqrtf(ux * ux + uy * uy);
            float c1, s1;
            if (rxy > 0.0f) { const float ir = 1.0f / rxy; c1 = ux * ir; s1 = uy * ir; }
            else            { c1 = 1.0f; s1 = 0.0f; }
            const float c2 = 2.0f * c1 * c1 - 1.0f;
            const float s2 = 2.0f * s1 * c1;
            const float c3 = c1 * c2 - s1 * s2;
            const float s3 = s1 * c2 + c1 * s2;

            const float P11 = -st;
            const float P22 = 3.0f * st2;
            const float P33 = -15.0f * st2 * st;
            const float P21 = -3.0f * ct * st;
            const float P32 = 15.0f * ct * st2;
            const float P20 = 1.5f * ct * ct - 0.5f;
            const float P31 = 0.5f * (5.0f * ct * P21 + 3.0f * st);
            const float P30 = ct * (2.5f * ct * ct - 1.5f);

            const float n00 = 0.28209479177f;
            const float n10 = 0.48860251190f, n11 = 0.34549414947f;
            const float n20 = 0.63078313051f, n21 = 0.25751613469f, n22 = 0.12875806734f;
            const float n30 = 0.74635266518f, n31 = 0.21545345607f, n32 = 0.06813236028f,
                        n33 = 0.02781492157f;

            const float a  = n11 * P11;
            const float b1 = n21 * P21, b2 = n22 * P22;
            const float d1 = n31 * P31, d2 = n32 * P32, d3 = n33 * P33;

            if (lane == 0) {
                s_ylr[warp][0] = make_float4(n00,      -a * c1,   n10 * ct,  a * c1);
                s_yli[warp][0] = make_float4(0.0f,      a * s1,   0.0f,      a * s1);
                s_ylr[warp][1] = make_float4(b2 * c2,  -b1 * c1,  n20 * P20, b1 * c1);
                s_yli[warp][1] = make_float4(-b2 * s2,  b1 * s1,  0.0f,      b1 * s1);
                s_ylr[warp][2] = make_float4(b2 * c2,  -d3 * c3,  d2 * c2,  -d1 * c1);
                s_yli[warp][2] = make_float4(b2 * s2,   d3 * s3, -d2 * s2,   d1 * s1);
                s_ylr[warp][3] = make_float4(n30 * P30, d1 * c1,  d2 * c2,   d3 * c3);
                s_yli[warp][3] = make_float4(0.0f,      d1 * s1,  d2 * s2,   d3 * s3);
            }
        }
        __syncwarp();

        // ---- scal[pair] = radial[i] * na[k], pair = k*8 + i ----
        #pragma unroll
        for (int p = lane; p < 80; p += 32) {
            s_scal[warp][p] = s_rad[warp][p & 7] * s_na[warp][p >> 3];
        }
        __syncwarp();

        // ---- 320 float4 per half, coalesced streaming stores ----
        const long long base_r = (long long)e * F4_PER_EDGE;
        const long long base_i = ((long long)E + e) * F4_PER_EDGE;

        #pragma unroll
        for (int it = 0; it < 10; ++it) {
            const int f    = lane + 32 * it;
            const int j4   = f & 3;
            const int pair = f >> 2;
            const float s  = s_scal[warp][pair];
            const float4 yr = s_ylr[warp][j4];
            const float4 yi = s_yli[warp][j4];
            float4 orr = make_float4(s * yr.x, s * yr.y, s * yr.z, s * yr.w);
            float4 oii = make_float4(s * yi.x, s * yi.y, s * yi.z, s * yi.w);
            __stcs(&out4[base_r + f], orr);
            __stcs(&out4[base_i + f], oii);
        }
        __syncwarp();   // shared rows reused next iteration
    }
}

extern "C" void kernel_launch(void* const* d_in, const int* in_sizes, int n_in,
                              void* d_out, int out_size)
{
    const int*   edge_index = (const int*)d_in[0];    // (2, E) int32
    const float* lens       = (const float*)d_in[1];  // (E, 1) f32
    const float* vecs       = (const float*)d_in[2];  // (E, 3) f32
    const float* attrs      = (const float*)d_in[3];  // (N_NODES, 10) f32
    float* out = (float*)d_out;

    const int E = in_sizes[1];   // edge_lenghts element count
    edge_embed_kernel<<<NCTAS, NWARPS_CTA * 32>>>(edge_index, lens, vecs, attrs, out, E);
}

// round 3
// speedup vs baseline: 1.0751x; 1.0751x over previous
#include <cuda_runtime.h>
#include <cuda_bf16.h>
#include <math.h>

// EdgeEmbeddingBlock: out_r[b,k,i,j] = radial[b,i] * na[b,k] * ylm_r[b,j]
//                     out_i[b,k,i,j] = radial[b,i] * na[b,k] * ylm_i[b,j]
// E=60000, K=10, NMAX=8, J=16. Output [combined_r | combined_i], 614 MB written.
//
// Fully register-resident: for float4 index f = lane + 32*it,
//   scale  = rad[lane>>2] * na[it]   (lane-invariant radial, shuffled na)
//   ylm4   = group (lane&3)          (fixed per lane for the whole edge)
// -> no shared memory, no syncs, 20 coalesced STG.128 per lane per edge.

#define KATTR 10
#define F4_PER_EDGE 320          // 1280 floats / 4

#define SEL4(g,a,b,c,d) ((g)==0?(a):((g)==1?(b):((g)==2?(c):(d))))

__global__ __launch_bounds__(256, 6)
void edge_embed_kernel(const int* __restrict__ edge_index,
                       const float* __restrict__ lens,
                       const float* __restrict__ vecs,
                       const float* __restrict__ attrs,
                       float* __restrict__ out,
                       int E)
{
    const int warp = threadIdx.x >> 5;
    const int lane = threadIdx.x & 31;
    const int e = blockIdx.x * 8 + warp;
    if (e >= E) return;

    // ---- per-edge scalars (broadcast loads) ----
    const float x  = lens[e];
    const float vx = vecs[3 * e + 0];
    const float vy = vecs[3 * e + 1];
    const float vz = vecs[3 * e + 2];
    const int sender = edge_index[e];   // edge_index[0, e]

    // lanes 0..9: node attrs for shuffle distribution
    float na_v = 0.0f;
    if (lane < KATTR) na_v = attrs[sender * KATTR + lane];

    // ---- radial: each lane computes rad[lane>>2] (poly cutoff p=6, R_CUT=5) ----
    const float u  = x * 0.2f;
    const float u2 = u * u, u3 = u2 * u;
    const float u6 = u3 * u3, u7 = u6 * u, u8 = u7 * u;
    float env = 1.0f - 28.0f * u6 + 48.0f * u7 - 21.0f * u8;
    env = (u < 1.0f) ? env : 0.0f;
    const float base = 0.63245553203f * env / x;          // sqrt(2/5) * env / x
    const float w = (float)((lane >> 2) + 1) * 0.62831853071f;  // n*pi/R_CUT
    const float r_l = base * sinf(w * x);

    // ---- zonal harmonics (all lanes, straight-line) ----
    const float nrm = sqrtf(vx * vx + vy * vy + vz * vz);
    const float inv = 1.0f / fmaxf(nrm, 1e-9f);
    const float ux = vx * inv, uy = vy * inv, uz = vz * inv;
    const float ct  = uz;
    const float st2 = fmaxf(1.0f - ct * ct, 0.0f);
    const float st  = sqrtf(st2);
    const float rxy = sqrtf(ux * ux + uy * uy);
    float c1, s1;
    if (rxy > 0.0f) { const float ir = 1.0f / rxy; c1 = ux * ir; s1 = uy * ir; }
    else            { c1 = 1.0f; s1 = 0.0f; }
    const float c2 = 2.0f * c1 * c1 - 1.0f;
    const float s2 = 2.0f * s1 * c1;
    const float c3 = c1 * c2 - s1 * s2;
    const float s3 = s1 * c2 + c1 * s2;

    const float P11 = -st;
    const float P22 = 3.0f * st2;
    const float P33 = -15.0f * st2 * st;
    const float P21 = -3.0f * ct * st;
    const float P32 = 15.0f * ct * st2;
    const float P20 = 1.5f * ct * ct - 0.5f;
    const float P31 = 0.5f * (5.0f * ct * P21 + 3.0f * st);
    const float P30 = ct * (2.5f * ct * ct - 1.5f);

    const float n00 = 0.28209479177f;
    const float n10 = 0.48860251190f, n11 = 0.34549414947f;
    const float n20 = 0.63078313051f, n21 = 0.25751613469f, n22 = 0.12875806734f;
    const float n30 = 0.74635266518f, n31 = 0.21545345607f, n32 = 0.06813236028f,
                n33 = 0.02781492157f;

    const float a  = n11 * P11;
    const float b1 = n21 * P21, b2 = n22 * P22;
    const float d1 = n31 * P31, d2 = n32 * P32, d3 = n33 * P33;

    // ylm groups (j = 4g .. 4g+3), select this lane's group g = lane & 3
    const int g = lane & 3;
    float4 yr4, yi4;
    yr4.x = SEL4(g, n00,       b2 * c2,   b2 * c2,  n30 * P30);
    yr4.y = SEL4(g, -a * c1,  -b1 * c1,  -d3 * c3,  d1 * c1);
    yr4.z = SEL4(g, n10 * ct,  n20 * P20, d2 * c2,  d2 * c2);
    yr4.w = SEL4(g, a * c1,    b1 * c1,  -d1 * c1,  d3 * c3);
    yi4.x = SEL4(g, 0.0f,     -b2 * s2,   b2 * s2,  0.0f);
    yi4.y = SEL4(g, a * s1,    b1 * s1,   d3 * s3,  d1 * s1);
    yi4.z = SEL4(g, 0.0f,      0.0f,     -d2 * s2,  d2 * s2);
    yi4.w = SEL4(g, a * s1,    b1 * s1,   d1 * s1,  d3 * s3);

    // ---- 320 float4 per half, coalesced streaming stores ----
    float4* __restrict__ out4 = (float4*)out;
    const long long base_r = (long long)e * F4_PER_EDGE + lane;
    const long long base_i = ((long long)E + e) * F4_PER_EDGE + lane;

    #pragma unroll
    for (int it = 0; it < KATTR; ++it) {
        const float s = r_l * __shfl_sync(0xffffffffu, na_v, it);
        float4 orr = make_float4(s * yr4.x, s * yr4.y, s * yr4.z, s * yr4.w);
        float4 oii = make_float4(s * yi4.x, s * yi4.y, s * yi4.z, s * yi4.w);
        __stcs(&out4[base_r + 32 * it], orr);
        __stcs(&out4[base_i + 32 * it], oii);
    }
}

extern "C" void kernel_launch(void* const* d_in, const int* in_sizes, int n_in,
                              void* d_out, int out_size)
{
    const int*   edge_index = (const int*)d_in[0];    // (2, E) int32
    const float* lens       = (const float*)d_in[1];  // (E, 1) f32
    const float* vecs       = (const float*)d_in[2];  // (E, 3) f32
    const float* attrs      = (const float*)d_in[3];  // (N_NODES, 10) f32
    float* out = (float*)d_out;

    const int E = in_sizes[1];   // edge_lenghts element count
    const int blocks = (E + 7) / 8;
    edge_embed_kernel<<<blocks, 256>>>(edge_index, lens, vecs, attrs, out, E);
}